// round 9
// baseline (speedup 1.0000x reference)
#include <cuda_runtime.h>

// ---------------------------------------------------------------------------
// FrequencyAwareEmbedding, round 9.  TWO launches, ZERO global atomics:
//   stage_b : one warp per 32-row strip of the 100k-row table.
//             - lane l copies row (strip*32+l) from emb0/1/2 if bucket<=2
//             - ballot bucket==3 / ==4, project matching rows in groups of 8
//               via smem-staged rows + LDS.128 broadcast (W amortized 8x)
//             No lists, no counters, no inter-block barrier.
//   gather  : out[t] = g_all[x[t]], 8 tokens / 8-thread group (MLP=8).
// ---------------------------------------------------------------------------

#define NROWS 100000
#define ODIM  32

#define PADK51  52
#define PADK102 104

__device__ __align__(256) float g_all[NROWS * ODIM];

// --- project the rows flagged in mask m (bucket match) in groups of <=8 ---
// All lanes of the warp participate; lane j owns output column j.
template <int K, int PADK>
__device__ __forceinline__ void proj_group(unsigned m, int row0,
                                           const float* __restrict__ emb,
                                           const float* __restrict__ W,
                                           const float* __restrict__ b,
                                           float* __restrict__ out,
                                           float* __restrict__ es,  // 8*PADK
                                           int lane)
{
    constexpr int CH = (PADK + 31) / 32;
    constexpr int Q  = (K + 3) / 4;

    int cnt = __popc(m);
    if (cnt == 0) return;

    float bias = __ldg(&b[lane]);

    for (int base = 0; base < cnt; base += 8) {
        int nv = cnt - base;
        if (nv > 8) nv = 8;

        int rws[8];
        #pragma unroll
        for (int g = 0; g < 8; ++g) {
            int idx = base + (g < nv ? g : 0);
            rws[g] = row0 + (int)__fns(m, 0, idx + 1);
        }

        __syncwarp();   // WAR vs previous group's LDS reads

        // Stage 8 rows into smem, coalesced; zero-fill the pad.
        #pragma unroll
        for (int g = 0; g < 8; ++g) {
            #pragma unroll
            for (int ch = 0; ch < CH; ++ch) {
                int k = ch * 32 + lane;
                if (k < PADK)
                    es[g * PADK + k] =
                        (k < K) ? __ldg(&emb[(size_t)rws[g] * K + k]) : 0.0f;
            }
        }
        __syncwarp();

        float acc[8];
        #pragma unroll
        for (int g = 0; g < 8; ++g) acc[g] = bias;

        #pragma unroll 4
        for (int q = 0; q < Q; ++q) {
            int k0 = q * 4;
            float w0 = __ldg(&W[(k0 + 0) * 32 + lane]);
            float w1 = (k0 + 1 < K) ? __ldg(&W[(k0 + 1) * 32 + lane]) : 0.0f;
            float w2 = (k0 + 2 < K) ? __ldg(&W[(k0 + 2) * 32 + lane]) : 0.0f;
            float w3 = (k0 + 3 < K) ? __ldg(&W[(k0 + 3) * 32 + lane]) : 0.0f;

            #pragma unroll
            for (int g = 0; g < 8; ++g) {
                float4 e4 = *reinterpret_cast<const float4*>(&es[g * PADK + k0]);
                acc[g] = fmaf(e4.x, w0, acc[g]);
                acc[g] = fmaf(e4.y, w1, acc[g]);
                acc[g] = fmaf(e4.z, w2, acc[g]);
                acc[g] = fmaf(e4.w, w3, acc[g]);
            }
        }

        #pragma unroll
        for (int g = 0; g < 8; ++g)
            if (g < nv)
                out[(size_t)rws[g] * ODIM + lane] = acc[g];
    }
}

__global__ void __launch_bounds__(256)
stage_b(const int*   __restrict__ bucket,
        const float* __restrict__ e0,
        const float* __restrict__ e1,
        const float* __restrict__ e2,
        const float* __restrict__ emb3,
        const float* __restrict__ W3,
        const float* __restrict__ b3,
        const float* __restrict__ emb4,
        const float* __restrict__ W4,
        const float* __restrict__ b4,
        float*       __restrict__ all_f,
        int rows)
{
    __shared__ __align__(16) float es[8][8 * PADK102];   // 26.6 KB

    int warp = threadIdx.x >> 5;
    int lane = threadIdx.x & 31;
    int strip = blockIdx.x * 8 + warp;
    int row0 = strip * 32;
    if (row0 >= rows) return;

    int r  = row0 + lane;
    int bk = (r < rows) ? __ldg(&bucket[r]) : -1;

    // ---- copy path: lane copies its whole row (8 float4, batched) ----
    if (bk >= 0 && bk <= 2) {
        const float4* t = (bk == 0) ? (const float4*)e0
                        : (bk == 1) ? (const float4*)e1
                                    : (const float4*)e2;
        float4 v[8];
        #pragma unroll
        for (int i = 0; i < 8; ++i)
            v[i] = __ldg(&t[(size_t)r * 8 + i]);
        #pragma unroll
        for (int i = 0; i < 8; ++i)
            reinterpret_cast<float4*>(all_f)[(size_t)r * 8 + i] = v[i];
    }

    // ---- projection paths ----
    unsigned m3 = __ballot_sync(0xffffffffu, bk == 3);
    unsigned m4 = __ballot_sync(0xffffffffu, bk == 4);

    proj_group<51,  PADK51 >(m3, row0, emb3, W3, b3, all_f, es[warp], lane);
    proj_group<102, PADK102>(m4, row0, emb4, W4, b4, all_f, es[warp], lane);
}

// 8-thread group handles EIGHT tokens (MLP=8).
__global__ void gather_kernel(const int4*   __restrict__ x4,
                              const float4* __restrict__ tab,
                              float4*       __restrict__ out,
                              int Tg)
{
    int gid = blockIdx.x * blockDim.x + threadIdx.x;
    int grp = gid >> 3;
    if (grp >= Tg) return;
    int c = gid & 7;

    int4 ia = __ldg(&x4[(size_t)grp * 2 + 0]);
    int4 ib = __ldg(&x4[(size_t)grp * 2 + 1]);

    float4 v0 = __ldg(&tab[(size_t)ia.x * 8 + c]);
    float4 v1 = __ldg(&tab[(size_t)ia.y * 8 + c]);
    float4 v2 = __ldg(&tab[(size_t)ia.z * 8 + c]);
    float4 v3 = __ldg(&tab[(size_t)ia.w * 8 + c]);
    float4 v4 = __ldg(&tab[(size_t)ib.x * 8 + c]);
    float4 v5 = __ldg(&tab[(size_t)ib.y * 8 + c]);
    float4 v6 = __ldg(&tab[(size_t)ib.z * 8 + c]);
    float4 v7 = __ldg(&tab[(size_t)ib.w * 8 + c]);

    size_t base = (size_t)grp * 64 + c;
    __stcs(&out[base +  0], v0);
    __stcs(&out[base +  8], v1);
    __stcs(&out[base + 16], v2);
    __stcs(&out[base + 24], v3);
    __stcs(&out[base + 32], v4);
    __stcs(&out[base + 40], v5);
    __stcs(&out[base + 48], v6);
    __stcs(&out[base + 56], v7);
}

extern "C" void kernel_launch(void* const* d_in, const int* in_sizes, int n_in,
                              void* d_out, int out_size)
{
    const int*   x      = (const int*)  d_in[0];
    const int*   bucket = (const int*)  d_in[1];
    const float* emb0   = (const float*)d_in[2];
    const float* emb1   = (const float*)d_in[3];
    const float* emb2   = (const float*)d_in[4];
    const float* emb3   = (const float*)d_in[5];
    const float* emb4   = (const float*)d_in[6];
    const float* W3     = (const float*)d_in[7];
    const float* b3     = (const float*)d_in[8];
    const float* W4     = (const float*)d_in[9];
    const float* b4     = (const float*)d_in[10];

    const int T    = in_sizes[0];          // 1,048,576 tokens (multiple of 8)
    const int rows = in_sizes[1];          // 100,000 (multiple of 32)

    float* all_f;
    cudaGetSymbolAddress((void**)&all_f, g_all);

    int strips  = (rows + 31) / 32;        // 3125
    int sblocks = (strips + 7) / 8;        // 391
    stage_b<<<sblocks, 256>>>(bucket, emb0, emb1, emb2,
                              emb3, W3, b3, emb4, W4, b4, all_f, rows);

    const int Tg = T / 8;
    long long gthreads_total = (long long)Tg * 8;
    int gblocks = (int)((gthreads_total + 255) / 256);
    gather_kernel<<<gblocks, 256>>>((const int4*)x, (const float4*)all_f,
                                    (float4*)d_out, Tg);
}

// round 10
// speedup vs baseline: 1.1983x; 1.1983x over previous
#include <cuda_runtime.h>

// ---------------------------------------------------------------------------
// FrequencyAwareEmbedding, round 10.  TWO launches, ZERO global state
// (except the combined table itself). Block-local compaction in smem.
//
//   stage_b : block = 256-row tile.
//     phase1: thread t owns row tile*256+t; copies it from emb0/1/2 if
//             bucket<=2; warp-ballot compacts bucket-3/4 row ids into
//             SMEM lists (one smem atomic per warp per bucket).
//     phase2: 8 warps round-robin the block's dense groups of 8 rows;
//             stage rows to smem, LDS.128 broadcast quad loop (FMA 4:1).
//   gather  : out[t] = g_all[x[t]], 8 tokens / 8-thread group (MLP=8).
// ---------------------------------------------------------------------------

#define NROWS 100000
#define ODIM  32

#define PADK51  52
#define PADK102 104

__device__ __align__(256) float g_all[NROWS * ODIM];

// --- project one dense group of <=8 rows (row ids in smem list) ---
// All lanes participate; lane j owns output column j.
template <int K, int PADK>
__device__ __forceinline__ void proj_group(const int* __restrict__ slist,
                                           int gbase, int cnt,
                                           const float* __restrict__ emb,
                                           const float* __restrict__ W,
                                           const float* __restrict__ b,
                                           float* __restrict__ out,
                                           float* __restrict__ es,  // 8*PADK
                                           int lane)
{
    constexpr int CH = (PADK + 31) / 32;
    constexpr int Q  = (K + 3) / 4;

    int nv = cnt - gbase;
    if (nv > 8) nv = 8;

    int rws[8];
    #pragma unroll
    for (int g = 0; g < 8; ++g)
        rws[g] = slist[gbase + (g < nv ? g : 0)];

    // Stage rows into smem (coalesced), zero-fill pad [K, PADK).
    #pragma unroll
    for (int g = 0; g < 8; ++g) {
        #pragma unroll
        for (int ch = 0; ch < CH; ++ch) {
            int k = ch * 32 + lane;
            if (k < PADK)
                es[g * PADK + k] =
                    (k < K) ? __ldg(&emb[(size_t)rws[g] * K + k]) : 0.0f;
        }
    }
    __syncwarp();

    float bias = __ldg(&b[lane]);
    float acc[8];
    #pragma unroll
    for (int g = 0; g < 8; ++g) acc[g] = bias;

    for (int q = 0; q < Q; ++q) {
        int k0 = q * 4;
        float w0 = __ldg(&W[(k0 + 0) * 32 + lane]);
        float w1 = (k0 + 1 < K) ? __ldg(&W[(k0 + 1) * 32 + lane]) : 0.0f;
        float w2 = (k0 + 2 < K) ? __ldg(&W[(k0 + 2) * 32 + lane]) : 0.0f;
        float w3 = (k0 + 3 < K) ? __ldg(&W[(k0 + 3) * 32 + lane]) : 0.0f;

        #pragma unroll
        for (int g = 0; g < 8; ++g) {
            float4 e4 = *reinterpret_cast<const float4*>(&es[g * PADK + k0]);
            acc[g] = fmaf(e4.x, w0, acc[g]);
            acc[g] = fmaf(e4.y, w1, acc[g]);
            acc[g] = fmaf(e4.z, w2, acc[g]);
            acc[g] = fmaf(e4.w, w3, acc[g]);
        }
    }
    __syncwarp();   // reads of es done before caller restages

    #pragma unroll
    for (int g = 0; g < 8; ++g)
        if (g < nv)
            out[(size_t)rws[g] * ODIM + lane] = acc[g];
}

__global__ void __launch_bounds__(256)
stage_b(const int*   __restrict__ bucket,
        const float* __restrict__ e0,
        const float* __restrict__ e1,
        const float* __restrict__ e2,
        const float* __restrict__ emb3,
        const float* __restrict__ W3,
        const float* __restrict__ b3,
        const float* __restrict__ emb4,
        const float* __restrict__ W4,
        const float* __restrict__ b4,
        float*       __restrict__ all_f,
        int rows)
{
    __shared__ __align__(16) float es[8][8 * PADK102];   // 26.6 KB
    __shared__ int sl3[256], sl4[256];
    __shared__ int sc3, sc4;

    int tid  = threadIdx.x;
    int warp = tid >> 5;
    int lane = tid & 31;

    if (tid == 0) { sc3 = 0; sc4 = 0; }
    __syncthreads();

    // ---- phase 1: copy + compact ----
    int r  = blockIdx.x * 256 + tid;
    int bk = (r < rows) ? __ldg(&bucket[r]) : -1;

    if (bk >= 0 && bk <= 2) {
        const float4* t = (bk == 0) ? (const float4*)e0
                        : (bk == 1) ? (const float4*)e1
                                    : (const float4*)e2;
        float4* dst = reinterpret_cast<float4*>(all_f) + (size_t)r * 8;
        float4 v[4];
        #pragma unroll
        for (int i = 0; i < 4; ++i) v[i] = __ldg(&t[(size_t)r * 8 + i]);
        #pragma unroll
        for (int i = 0; i < 4; ++i) dst[i] = v[i];
        #pragma unroll
        for (int i = 0; i < 4; ++i) v[i] = __ldg(&t[(size_t)r * 8 + 4 + i]);
        #pragma unroll
        for (int i = 0; i < 4; ++i) dst[4 + i] = v[i];
    }

    unsigned m3 = __ballot_sync(0xffffffffu, bk == 3);
    unsigned m4 = __ballot_sync(0xffffffffu, bk == 4);
    unsigned lt = (1u << lane) - 1u;

    if (bk == 3) {
        int base = 0;
        if (__ffs(m3) - 1 == lane) base = atomicAdd(&sc3, __popc(m3));
        base = __shfl_sync(m3, base, __ffs(m3) - 1);
        sl3[base + __popc(m3 & lt)] = r;
    }
    if (bk == 4) {
        int base = 0;
        if (__ffs(m4) - 1 == lane) base = atomicAdd(&sc4, __popc(m4));
        base = __shfl_sync(m4, base, __ffs(m4) - 1);
        sl4[base + __popc(m4 & lt)] = r;
    }
    __syncthreads();

    // ---- phase 2: dense projection, warps round-robin groups ----
    int n3 = sc3, n4 = sc4;
    int n3g = (n3 + 7) >> 3;
    int n4g = (n4 + 7) >> 3;
    int ng  = n3g + n4g;

    for (int g = warp; g < ng; g += 8) {
        if (g < n3g)
            proj_group<51,  PADK51 >(sl3, g * 8, n3, emb3, W3, b3,
                                     all_f, es[warp], lane);
        else
            proj_group<102, PADK102>(sl4, (g - n3g) * 8, n4, emb4, W4, b4,
                                     all_f, es[warp], lane);
    }
}

// 8-thread group handles EIGHT tokens (MLP=8).
__global__ void gather_kernel(const int4*   __restrict__ x4,
                              const float4* __restrict__ tab,
                              float4*       __restrict__ out,
                              int Tg)
{
    int gid = blockIdx.x * blockDim.x + threadIdx.x;
    int grp = gid >> 3;
    if (grp >= Tg) return;
    int c = gid & 7;

    int4 ia = __ldg(&x4[(size_t)grp * 2 + 0]);
    int4 ib = __ldg(&x4[(size_t)grp * 2 + 1]);

    float4 v0 = __ldg(&tab[(size_t)ia.x * 8 + c]);
    float4 v1 = __ldg(&tab[(size_t)ia.y * 8 + c]);
    float4 v2 = __ldg(&tab[(size_t)ia.z * 8 + c]);
    float4 v3 = __ldg(&tab[(size_t)ia.w * 8 + c]);
    float4 v4 = __ldg(&tab[(size_t)ib.x * 8 + c]);
    float4 v5 = __ldg(&tab[(size_t)ib.y * 8 + c]);
    float4 v6 = __ldg(&tab[(size_t)ib.z * 8 + c]);
    float4 v7 = __ldg(&tab[(size_t)ib.w * 8 + c]);

    size_t base = (size_t)grp * 64 + c;
    __stcs(&out[base +  0], v0);
    __stcs(&out[base +  8], v1);
    __stcs(&out[base + 16], v2);
    __stcs(&out[base + 24], v3);
    __stcs(&out[base + 32], v4);
    __stcs(&out[base + 40], v5);
    __stcs(&out[base + 48], v6);
    __stcs(&out[base + 56], v7);
}

extern "C" void kernel_launch(void* const* d_in, const int* in_sizes, int n_in,
                              void* d_out, int out_size)
{
    const int*   x      = (const int*)  d_in[0];
    const int*   bucket = (const int*)  d_in[1];
    const float* emb0   = (const float*)d_in[2];
    const float* emb1   = (const float*)d_in[3];
    const float* emb2   = (const float*)d_in[4];
    const float* emb3   = (const float*)d_in[5];
    const float* emb4   = (const float*)d_in[6];
    const float* W3     = (const float*)d_in[7];
    const float* b3     = (const float*)d_in[8];
    const float* W4     = (const float*)d_in[9];
    const float* b4     = (const float*)d_in[10];

    const int T    = in_sizes[0];          // 1,048,576 tokens (multiple of 8)
    const int rows = in_sizes[1];          // 100,000

    float* all_f;
    cudaGetSymbolAddress((void**)&all_f, g_all);

    int sblocks = (rows + 255) / 256;      // 391
    stage_b<<<sblocks, 256>>>(bucket, emb0, emb1, emb2,
                              emb3, W3, b3, emb4, W4, b4, all_f, rows);

    const int Tg = T / 8;
    long long gthreads_total = (long long)Tg * 8;
    int gblocks = (int)((gthreads_total + 255) / 256);
    gather_kernel<<<gblocks, 256>>>((const int4*)x, (const float4*)all_f,
                                    (float4*)d_out, Tg);
}

// round 11
// speedup vs baseline: 1.2539x; 1.0464x over previous
#include <cuda_runtime.h>

// ---------------------------------------------------------------------------
// FrequencyAwareEmbedding, round 11.  TWO launches, block-local smem
// compaction, COALESCED copy (8 threads/row -> 4 L1 wavefronts per LDG.128
// instead of 32 in round 10).
//
//   stage_b : block = 256-row tile.
//     phase0: thread t scans bucket[tile*256+t]; ballot-compact rows into
//             smem lists: sl3 (bk==3), sl4 (bk==4), slc (bk<=2, packed
//             (r<<2)|bk).
//     phase1: cooperative coalesced copy of slc rows (8 threads per row).
//     phase2: warps round-robin dense groups of 8 rows; stage to smem,
//             LDS.128 broadcast quad loop (FMA 4:1).
//   gather  : out[t] = g_all[x[t]], 8 tokens / 8-thread group (MLP=8).
// ---------------------------------------------------------------------------

#define NROWS 100000
#define ODIM  32

#define PADK51  52
#define PADK102 104

__device__ __align__(256) float g_all[NROWS * ODIM];

// --- project one dense group of <=8 rows (row ids in smem list) ---
template <int K, int PADK>
__device__ __forceinline__ void proj_group(const int* __restrict__ slist,
                                           int gbase, int cnt,
                                           const float* __restrict__ emb,
                                           const float* __restrict__ W,
                                           const float* __restrict__ b,
                                           float* __restrict__ out,
                                           float* __restrict__ es,  // 8*PADK
                                           int lane)
{
    constexpr int CH = (PADK + 31) / 32;
    constexpr int Q  = (K + 3) / 4;

    int nv = cnt - gbase;
    if (nv > 8) nv = 8;

    int rws[8];
    #pragma unroll
    for (int g = 0; g < 8; ++g)
        rws[g] = slist[gbase + (g < nv ? g : 0)];

    // Stage rows into smem (coalesced), zero-fill pad [K, PADK).
    #pragma unroll
    for (int g = 0; g < 8; ++g) {
        #pragma unroll
        for (int ch = 0; ch < CH; ++ch) {
            int k = ch * 32 + lane;
            if (k < PADK)
                es[g * PADK + k] =
                    (k < K) ? __ldg(&emb[(size_t)rws[g] * K + k]) : 0.0f;
        }
    }
    __syncwarp();

    float bias = __ldg(&b[lane]);
    float acc[8];
    #pragma unroll
    for (int g = 0; g < 8; ++g) acc[g] = bias;

    #pragma unroll
    for (int q = 0; q < Q; ++q) {
        int k0 = q * 4;
        float w0 = __ldg(&W[(k0 + 0) * 32 + lane]);
        float w1 = (k0 + 1 < K) ? __ldg(&W[(k0 + 1) * 32 + lane]) : 0.0f;
        float w2 = (k0 + 2 < K) ? __ldg(&W[(k0 + 2) * 32 + lane]) : 0.0f;
        float w3 = (k0 + 3 < K) ? __ldg(&W[(k0 + 3) * 32 + lane]) : 0.0f;

        #pragma unroll
        for (int g = 0; g < 8; ++g) {
            float4 e4 = *reinterpret_cast<const float4*>(&es[g * PADK + k0]);
            acc[g] = fmaf(e4.x, w0, acc[g]);
            acc[g] = fmaf(e4.y, w1, acc[g]);
            acc[g] = fmaf(e4.z, w2, acc[g]);
            acc[g] = fmaf(e4.w, w3, acc[g]);
        }
    }
    __syncwarp();   // reads of es done before caller restages

    #pragma unroll
    for (int g = 0; g < 8; ++g)
        if (g < nv)
            out[(size_t)rws[g] * ODIM + lane] = acc[g];
}

__global__ void __launch_bounds__(256)
stage_b(const int*   __restrict__ bucket,
        const float* __restrict__ e0,
        const float* __restrict__ e1,
        const float* __restrict__ e2,
        const float* __restrict__ emb3,
        const float* __restrict__ W3,
        const float* __restrict__ b3,
        const float* __restrict__ emb4,
        const float* __restrict__ W4,
        const float* __restrict__ b4,
        float*       __restrict__ all_f,
        int rows)
{
    __shared__ __align__(16) float es[8][8 * PADK102];   // 26.6 KB
    __shared__ int sl3[256], sl4[256], slc[256];
    __shared__ int sc3, sc4, scc;

    int tid  = threadIdx.x;
    int warp = tid >> 5;
    int lane = tid & 31;

    if (tid == 0) { sc3 = 0; sc4 = 0; scc = 0; }
    __syncthreads();

    // ---- phase 0: scan + compact ----
    int r  = blockIdx.x * 256 + tid;
    int bk = (r < rows) ? __ldg(&bucket[r]) : -1;

    unsigned m3 = __ballot_sync(0xffffffffu, bk == 3);
    unsigned m4 = __ballot_sync(0xffffffffu, bk == 4);
    unsigned mc = __ballot_sync(0xffffffffu, bk >= 0 && bk <= 2);
    unsigned lt = (1u << lane) - 1u;

    if (bk == 3) {
        int base = 0;
        int ldr = __ffs(m3) - 1;
        if (lane == ldr) base = atomicAdd(&sc3, __popc(m3));
        base = __shfl_sync(m3, base, ldr);
        sl3[base + __popc(m3 & lt)] = r;
    }
    if (bk == 4) {
        int base = 0;
        int ldr = __ffs(m4) - 1;
        if (lane == ldr) base = atomicAdd(&sc4, __popc(m4));
        base = __shfl_sync(m4, base, ldr);
        sl4[base + __popc(m4 & lt)] = r;
    }
    if (bk >= 0 && bk <= 2) {
        int base = 0;
        int ldr = __ffs(mc) - 1;
        if (lane == ldr) base = atomicAdd(&scc, __popc(mc));
        base = __shfl_sync(mc, base, ldr);
        slc[base + __popc(mc & lt)] = (r << 2) | bk;
    }
    __syncthreads();

    // ---- phase 1: coalesced copy (8 threads per row, 2-way batched) ----
    {
        int nc = scc;
        int c  = tid & 7;
        for (int j = tid >> 3; j < nc; j += 64) {
            int p0 = slc[j];
            bool ok1 = (j + 32) < nc;
            int p1 = slc[ok1 ? j + 32 : j];

            int r0 = p0 >> 2, b0 = p0 & 3;
            int r1 = p1 >> 2, b1 = p1 & 3;

            const float4* t0 = (b0 == 0) ? (const float4*)e0
                             : (b0 == 1) ? (const float4*)e1
                                         : (const float4*)e2;
            const float4* t1 = (b1 == 0) ? (const float4*)e0
                             : (b1 == 1) ? (const float4*)e1
                                         : (const float4*)e2;

            float4 v0 = __ldg(&t0[(size_t)r0 * 8 + c]);
            float4 v1 = __ldg(&t1[(size_t)r1 * 8 + c]);

            reinterpret_cast<float4*>(all_f)[(size_t)r0 * 8 + c] = v0;
            if (ok1)
                reinterpret_cast<float4*>(all_f)[(size_t)r1 * 8 + c] = v1;
        }
    }

    // ---- phase 2: dense projection, warps round-robin groups ----
    int n3 = sc3, n4 = sc4;
    int n3g = (n3 + 7) >> 3;
    int n4g = (n4 + 7) >> 3;
    int ng  = n3g + n4g;

    for (int g = warp; g < ng; g += 8) {
        if (g < n3g)
            proj_group<51,  PADK51 >(sl3, g * 8, n3, emb3, W3, b3,
                                     all_f, es[warp], lane);
        else
            proj_group<102, PADK102>(sl4, (g - n3g) * 8, n4, emb4, W4, b4,
                                     all_f, es[warp], lane);
    }
}

// 8-thread group handles EIGHT tokens (MLP=8).
__global__ void gather_kernel(const int4*   __restrict__ x4,
                              const float4* __restrict__ tab,
                              float4*       __restrict__ out,
                              int Tg)
{
    int gid = blockIdx.x * blockDim.x + threadIdx.x;
    int grp = gid >> 3;
    if (grp >= Tg) return;
    int c = gid & 7;

    int4 ia = __ldg(&x4[(size_t)grp * 2 + 0]);
    int4 ib = __ldg(&x4[(size_t)grp * 2 + 1]);

    float4 v0 = __ldg(&tab[(size_t)ia.x * 8 + c]);
    float4 v1 = __ldg(&tab[(size_t)ia.y * 8 + c]);
    float4 v2 = __ldg(&tab[(size_t)ia.z * 8 + c]);
    float4 v3 = __ldg(&tab[(size_t)ia.w * 8 + c]);
    float4 v4 = __ldg(&tab[(size_t)ib.x * 8 + c]);
    float4 v5 = __ldg(&tab[(size_t)ib.y * 8 + c]);
    float4 v6 = __ldg(&tab[(size_t)ib.z * 8 + c]);
    float4 v7 = __ldg(&tab[(size_t)ib.w * 8 + c]);

    size_t base = (size_t)grp * 64 + c;
    __stcs(&out[base +  0], v0);
    __stcs(&out[base +  8], v1);
    __stcs(&out[base + 16], v2);
    __stcs(&out[base + 24], v3);
    __stcs(&out[base + 32], v4);
    __stcs(&out[base + 40], v5);
    __stcs(&out[base + 48], v6);
    __stcs(&out[base + 56], v7);
}

extern "C" void kernel_launch(void* const* d_in, const int* in_sizes, int n_in,
                              void* d_out, int out_size)
{
    const int*   x      = (const int*)  d_in[0];
    const int*   bucket = (const int*)  d_in[1];
    const float* emb0   = (const float*)d_in[2];
    const float* emb1   = (const float*)d_in[3];
    const float* emb2   = (const float*)d_in[4];
    const float* emb3   = (const float*)d_in[5];
    const float* emb4   = (const float*)d_in[6];
    const float* W3     = (const float*)d_in[7];
    const float* b3     = (const float*)d_in[8];
    const float* W4     = (const float*)d_in[9];
    const float* b4     = (const float*)d_in[10];

    const int T    = in_sizes[0];          // 1,048,576 tokens (multiple of 8)
    const int rows = in_sizes[1];          // 100,000

    float* all_f;
    cudaGetSymbolAddress((void**)&all_f, g_all);

    int sblocks = (rows + 255) / 256;      // 391
    stage_b<<<sblocks, 256>>>(bucket, emb0, emb1, emb2,
                              emb3, W3, b3, emb4, W4, b4, all_f, rows);

    const int Tg = T / 8;
    long long gthreads_total = (long long)Tg * 8;
    int gblocks = (int)((gthreads_total + 255) / 256);
    gather_kernel<<<gblocks, 256>>>((const int4*)x, (const float4*)all_f,
                                    (float4*)d_out, Tg);
}